// round 14
// baseline (speedup 1.0000x reference)
#include <cuda_runtime.h>
#include <cstddef>

// ---------------------------------------------------------------------------
// StockPredictor: 2-layer LSTM (B=256, T=2048, D=1, H1=128, H2=64) + FC head.
// R14: balanced pipeline on all 148 SMs, 512-thread blocks (128-reg cap =>
// no silent spills), audited weight splits keeping crossbar < FMA floor.
//   Producers (86): 84 x NB=3 + 2 x NB=2. 1 row/thread (512 rows),
//                   weights 64 smem cols (pitch 68) + 64 reg floats.
//   Consumers (62): 54 x NB=4 + 8 x NB=5. 2 parts x 256 rows (batch split),
//                   concat weights 80 reg + 112 smem (pitch 116).
// Per-batch flags, release/acquire; polite polling; end handshake resets.
// ---------------------------------------------------------------------------

constexpr int T  = 2048;
constexpr int B  = 256;
constexpr int H1 = 128;
constexpr int G1 = 512;
constexpr int H2 = 64;
constexpr int G2 = 256;

constexpr int P_PITCH = 68;    // 17*16B odd -> conflict-free LDS.128
constexpr int C_PITCH = 116;   // 29*16B odd -> conflict-free

// producer smem (NB=3 worst): Ws 512*68=34816f | xs 3*2048=6144f | hs 384f | gs 1536f
constexpr size_t SMEM_BYTES = (size_t)(34816 + 6144 + 384 + 1536) * 4; // 171520

__device__ float g_h1seq[(size_t)B * T * H1];
__device__ int   g_flag[B];
__device__ int   g_done[B];

// ---------------------------------------------------------------------------
__device__ __forceinline__ void fma2(unsigned long long& acc,
                                     unsigned long long a,
                                     unsigned long long b) {
    asm("fma.rn.f32x2 %0, %1, %2, %0;" : "+l"(acc) : "l"(a), "l"(b));
}
__device__ __forceinline__ float f32x2_sum2(unsigned long long u,
                                            unsigned long long v) {
    unsigned long long s;
    asm("add.rn.f32x2 %0, %1, %2;" : "=l"(s) : "l"(u), "l"(v));
    float lo, hi;
    asm("mov.b64 {%0, %1}, %2;" : "=f"(lo), "=f"(hi) : "l"(s));
    return lo + hi;
}
__device__ __forceinline__ float sigmoid_fast(float x) {
    return __fdividef(1.0f, 1.0f + __expf(-x));
}
__device__ __forceinline__ float tanh_acc(float x) {
    return fmaf(2.0f, sigmoid_fast(2.0f * x), -1.0f);
}
__device__ __forceinline__ int ld_acquire(const int* p) {
    int v;
    asm volatile("ld.acquire.gpu.global.b32 %0, [%1];" : "=r"(v) : "l"(p) : "memory");
    return v;
}
__device__ __forceinline__ void st_release(int* p, int v) {
    asm volatile("st.release.gpu.global.b32 [%0], %1;" :: "l"(p), "r"(v) : "memory");
}

// ---------------------------------------------------------------------------
// PRODUCER: layer 1, NB batches, 512 threads, row r = tid.
// ---------------------------------------------------------------------------
template <int NB>
__device__ __forceinline__ void producer_body(
    float* sm, int bg,
    const float* __restrict__ x,
    const float* __restrict__ W_ih1,
    const float* __restrict__ W_hh1,
    const float* __restrict__ b_ih1,
    const float* __restrict__ b_hh1)
{
    float* Ws = sm;                      // [512][P_PITCH] cols [0,64)
    float* xs = Ws + G1 * P_PITCH;       // [NB][T]
    float* hs = xs + NB * T;             // [NB][H1]
    float* gs = hs + NB * H1;            // [NB][G1]

    const int tid = threadIdx.x;
    const int r = tid;

    for (int i = tid; i < G1 * 64; i += 512) {
        int rr = i >> 6, c = i & 63;
        Ws[rr * P_PITCH + c] = W_hh1[rr * H1 + c];
    }
    // reg weights: cols [64,128) = 16 u2
    ulonglong2 wr[16];
    {
        const ulonglong2* s = reinterpret_cast<const ulonglong2*>(W_hh1 + r * H1 + 64);
        #pragma unroll
        for (int j = 0; j < 16; j++) wr[j] = s[j];
    }
    const float wx   = W_ih1[r];
    const float bias = b_ih1[r] + b_hh1[r];

    for (int i = tid; i < NB * T; i += 512)
        xs[i] = x[(size_t)bg * T + i];
    for (int i = tid; i < NB * H1; i += 512)
        hs[i] = 0.0f;
    __syncthreads();

    float cst = 0.0f;                    // update slot tid (if tid < NB*128)
    const bool is_upd = (tid < NB * H1);
    const int ub = tid >> 7, um = tid & (H1 - 1);
    const bool is_g = (r >= 256) && (r < 384);

    const ulonglong2* ws = reinterpret_cast<const ulonglong2*>(Ws + r * P_PITCH);

    for (int t = 0; t < T; t++) {
        unsigned long long acc[2 * NB];
        #pragma unroll
        for (int j = 0; j < 2 * NB; j++) acc[j] = 0ull;

        #pragma unroll
        for (int i = 0; i < 16; i++) {                // cols [0,64), smem w
            ulonglong2 w = ws[i];
            #pragma unroll
            for (int bb = 0; bb < NB; bb++) {
                ulonglong2 q = reinterpret_cast<const ulonglong2*>(hs + bb * H1)[i];
                fma2(acc[2 * bb], w.x, q.x); fma2(acc[2 * bb + 1], w.y, q.y);
            }
        }
        #pragma unroll
        for (int i = 0; i < 16; i++) {                // cols [64,128), reg w
            ulonglong2 w = wr[i];
            #pragma unroll
            for (int bb = 0; bb < NB; bb++) {
                ulonglong2 q = reinterpret_cast<const ulonglong2*>(hs + bb * H1 + 64)[i];
                fma2(acc[2 * bb], w.x, q.x); fma2(acc[2 * bb + 1], w.y, q.y);
            }
        }

        #pragma unroll
        for (int bb = 0; bb < NB; bb++) {
            float v = fmaf(xs[bb * T + t], wx, bias)
                      + f32x2_sum2(acc[2 * bb], acc[2 * bb + 1]);
            gs[bb * G1 + r] = is_g ? tanh_acc(v) : sigmoid_fast(v);
        }
        __syncthreads();

        if (is_upd) {
            const float* gb = gs + ub * G1;
            float i_ = gb[um], f_ = gb[H1 + um], g_ = gb[2 * H1 + um], o_ = gb[3 * H1 + um];
            cst = fmaf(f_, cst, i_ * g_);
            float h = o_ * tanh_acc(cst);
            hs[tid] = h;
            g_h1seq[((size_t)(bg + ub) * T + t) * H1 + um] = h;
        }
        __syncthreads();
        if (tid < NB) st_release(&g_flag[bg + tid], t + 1);
    }

    if (tid < NB) {
        while (ld_acquire(&g_done[bg + tid]) == 0) { __nanosleep(128); }
        g_flag[bg + tid] = 0;
        g_done[bg + tid] = 0;
    }
}

// ---------------------------------------------------------------------------
// CONSUMER: layer 2 + FC, NB batches, 512 threads.
// part = tid>>8: part0 handles batches [0, NBA), part1 [NBA, NB).
// Row r = tid&255 over concat state [h1(128)|h2(64)].
// ---------------------------------------------------------------------------
template <int NB>
__device__ __forceinline__ void consumer_body(
    float* sm, int bg,
    const float* __restrict__ W_ih2,
    const float* __restrict__ W_hh2,
    const float* __restrict__ b_ih2,
    const float* __restrict__ b_hh2,
    const float* __restrict__ W_fc1,
    const float* __restrict__ b_fc1,
    const float* __restrict__ W_fc2,
    const float* __restrict__ b_fc2,
    float* __restrict__ out)
{
    constexpr int NBA = NB - NB / 2;     // part0 batch count
    constexpr int NBB = NB / 2;          // part1 batch count
    constexpr int NMAX = NBA;            // >= NBB

    float* Ws2   = sm;                   // [256][C_PITCH] concat cols [80,192)
    float* hcat  = Ws2 + G2 * C_PITCH;   // [NB][192] = h1 | h2
    float* gs2   = hcat + NB * 192;      // [NB][256]
    float* bsm   = gs2 + NB * G2;        // [256]
    float* stage = bsm + G2;             // [NB*32]

    const int tid  = threadIdx.x;
    const int part = tid >> 8;
    const int r    = tid & 255;
    const int bbase_p = (part == 0) ? 0 : NBA;
    const int nb_p    = (part == 0) ? NBA : NBB;

    // smem weight table: concat cols [80,192) = 112 cols
    for (int i = tid; i < G2 * 112; i += 512) {
        int rr = i / 112, c = i - rr * 112;
        float v = (c < 48) ? W_ih2[rr * H1 + 80 + c] : W_hh2[rr * H2 + (c - 48)];
        Ws2[rr * C_PITCH + c] = v;
    }
    // reg weights: concat [0,80) = W_ih2[r][0:80) = 20 u2
    ulonglong2 wr[20];
    {
        const ulonglong2* s = reinterpret_cast<const ulonglong2*>(W_ih2 + r * H1);
        #pragma unroll
        for (int j = 0; j < 20; j++) wr[j] = s[j];
    }
    if (tid < G2) bsm[tid] = b_ih2[tid] + b_hh2[tid];
    for (int i = tid; i < NB * 192; i += 512) hcat[i] = 0.0f;
    __syncthreads();

    // pre-loop: wait for h1(0), then stage it
    if (tid >= 507 && (tid - 507) < NB) {
        while (ld_acquire(&g_flag[bg + (tid - 507)]) < 1) { __nanosleep(64); }
    }
    __syncthreads();
    for (int s = tid; s < NB * H1; s += 512) {
        int bb = s >> 7, m = s & (H1 - 1);
        hcat[bb * 192 + m] = __ldcg(&g_h1seq[((size_t)(bg + bb) * T + 0) * H1 + m]);
    }
    __syncthreads();

    float cst = 0.0f;                    // update slot (if tid < NB*64)
    const bool is_upd = (tid < NB * H2);
    const int ub = tid >> 6, um = tid & (H2 - 1);
    const bool is_g = (r >= 2 * H2) && (r < 3 * H2);
    const ulonglong2* ws = reinterpret_cast<const ulonglong2*>(Ws2 + r * C_PITCH);

    for (int t = 0; t < T; t++) {
        // poll for NEXT step's h1 readiness during FMA phase (5 pollers)
        if (t + 1 < T && tid >= 507 && (tid - 507) < NB) {
            while (ld_acquire(&g_flag[bg + (tid - 507)]) < t + 2) { __nanosleep(32); }
        }

        unsigned long long acc[2 * NMAX];
        #pragma unroll
        for (int j = 0; j < 2 * NMAX; j++) acc[j] = 0ull;

        #pragma unroll
        for (int i = 0; i < 20; i++) {                // concat [0,80), reg w
            ulonglong2 w = wr[i];
            #pragma unroll
            for (int bb = 0; bb < NMAX; bb++) {
                if (bb < nb_p) {
                    ulonglong2 q = reinterpret_cast<const ulonglong2*>(
                        hcat + (bbase_p + bb) * 192)[i];
                    fma2(acc[2 * bb], w.x, q.x); fma2(acc[2 * bb + 1], w.y, q.y);
                }
            }
        }
        #pragma unroll
        for (int i = 0; i < 28; i++) {                // concat [80,192), smem w
            ulonglong2 w = ws[i];
            #pragma unroll
            for (int bb = 0; bb < NMAX; bb++) {
                if (bb < nb_p) {
                    ulonglong2 q = reinterpret_cast<const ulonglong2*>(
                        hcat + (bbase_p + bb) * 192 + 80)[i];
                    fma2(acc[2 * bb], w.x, q.x); fma2(acc[2 * bb + 1], w.y, q.y);
                }
            }
        }

        #pragma unroll
        for (int bb = 0; bb < NMAX; bb++) {
            if (bb < nb_p) {
                float v = bsm[r] + f32x2_sum2(acc[2 * bb], acc[2 * bb + 1]);
                gs2[(bbase_p + bb) * G2 + r] = is_g ? tanh_acc(v) : sigmoid_fast(v);
            }
        }
        __syncthreads();

        // phase B: update h2 + stage h1(t+1)
        if (is_upd) {
            const float* gb = gs2 + ub * G2;
            float i_ = gb[um], f_ = gb[H2 + um], g_ = gb[2 * H2 + um], o_ = gb[3 * H2 + um];
            cst = fmaf(f_, cst, i_ * g_);
            hcat[ub * 192 + H1 + um] = o_ * tanh_acc(cst);
        }
        if (t + 1 < T) {
            for (int s = tid; s < NB * H1; s += 512) {
                int bb = s >> 7, m = s & (H1 - 1);
                hcat[bb * 192 + m] =
                    __ldcg(&g_h1seq[((size_t)(bg + bb) * T + (t + 1)) * H1 + m]);
            }
        }
        __syncthreads();
    }

    // ---- FC head on final h2 (unroll-limited; cold code) ----
    if (tid < NB * 25) {
        int bb = tid / 25;
        int i  = tid - bb * 25;
        float a = b_fc1[i];
        #pragma unroll 4
        for (int k = 0; k < H2; k++)
            a = fmaf(W_fc1[i * H2 + k], hcat[bb * 192 + H1 + k], a);
        stage[bb * 32 + i] = a;
    }
    __syncthreads();
    if (tid < NB) {
        float a = b_fc2[0];
        #pragma unroll 5
        for (int i = 0; i < 25; i++)
            a = fmaf(W_fc2[i], stage[tid * 32 + i], a);
        out[bg + tid] = a;
        st_release(&g_done[bg + tid], 1);
    }
}

// ---------------------------------------------------------------------------
__global__ __launch_bounds__(512, 1)
void fused_lstm_kernel(const float* __restrict__ x,
                       const float* __restrict__ W_ih1,
                       const float* __restrict__ W_hh1,
                       const float* __restrict__ b_ih1,
                       const float* __restrict__ b_hh1,
                       const float* __restrict__ W_ih2,
                       const float* __restrict__ W_hh2,
                       const float* __restrict__ b_ih2,
                       const float* __restrict__ b_hh2,
                       const float* __restrict__ W_fc1,
                       const float* __restrict__ b_fc1,
                       const float* __restrict__ W_fc2,
                       const float* __restrict__ b_fc2,
                       float* __restrict__ out)
{
    extern __shared__ float sm[];
    const int bid = blockIdx.x;

    if (bid < 84) {
        producer_body<3>(sm, bid * 3, x, W_ih1, W_hh1, b_ih1, b_hh1);
    } else if (bid < 86) {
        producer_body<2>(sm, 252 + (bid - 84) * 2, x, W_ih1, W_hh1, b_ih1, b_hh1);
    } else if (bid < 140) {
        consumer_body<4>(sm, (bid - 86) * 4, W_ih2, W_hh2, b_ih2, b_hh2,
                         W_fc1, b_fc1, W_fc2, b_fc2, out);
    } else {
        consumer_body<5>(sm, 216 + (bid - 140) * 5, W_ih2, W_hh2, b_ih2, b_hh2,
                         W_fc1, b_fc1, W_fc2, b_fc2, out);
    }
}

// ---------------------------------------------------------------------------
extern "C" void kernel_launch(void* const* d_in, const int* in_sizes, int n_in,
                              void* d_out, int out_size)
{
    const float* x     = (const float*)d_in[0];
    const float* W_ih1 = (const float*)d_in[1];
    const float* W_hh1 = (const float*)d_in[2];
    const float* b_ih1 = (const float*)d_in[3];
    const float* b_hh1 = (const float*)d_in[4];
    const float* W_ih2 = (const float*)d_in[5];
    const float* W_hh2 = (const float*)d_in[6];
    const float* b_ih2 = (const float*)d_in[7];
    const float* b_hh2 = (const float*)d_in[8];
    const float* W_fc1 = (const float*)d_in[9];
    const float* b_fc1 = (const float*)d_in[10];
    const float* W_fc2 = (const float*)d_in[11];
    const float* b_fc2 = (const float*)d_in[12];
    float* out = (float*)d_out;

    static bool attr_done = false;
    if (!attr_done) {
        cudaFuncSetAttribute(fused_lstm_kernel,
                             cudaFuncAttributeMaxDynamicSharedMemorySize, (int)SMEM_BYTES);
        attr_done = true;
    }

    fused_lstm_kernel<<<148, 512, SMEM_BYTES>>>(
        x, W_ih1, W_hh1, b_ih1, b_hh1,
        W_ih2, W_hh2, b_ih2, b_hh2,
        W_fc1, b_fc1, W_fc2, b_fc2, out);
}

// round 15
// speedup vs baseline: 1.2972x; 1.2972x over previous
#include <cuda_runtime.h>
#include <cstddef>

// ---------------------------------------------------------------------------
// StockPredictor: 2-layer LSTM (B=256, T=2048, D=1, H1=128, H2=64) + FC head.
// R15 = R9 (best measured: 64 producers / 64 consumers x 4 batches, 256 thr)
// with ONE change: producer gate exchange moved from smem+2 barriers to a
// lane-pair warp shuffle + double-buffered h state => 1 barrier per step.
//   even lane owns rows {m, m+256} (i,g); odd lane owns {m+128, m+384} (f,o);
//   shfl_xor(1) delivers f,o to the even lane which updates c,h for slot m.
// Consumer is R9-verbatim (FC head unroll-limited).
// ---------------------------------------------------------------------------

constexpr int T  = 2048;
constexpr int B  = 256;
constexpr int H1 = 128;
constexpr int G1 = 512;
constexpr int H2 = 64;
constexpr int G2 = 256;
constexpr int NP = 64;
constexpr int NC = 64;
constexpr int BBP = 4;

// producer weight split: smem cols [0,64) pitch 68, reg cols [64,128)
constexpr int P_PITCH = 68;                 // 17*16B odd -> conflict-free
constexpr int P_WS  = 0;                    // [512][68]
constexpr int P_XS  = G1 * P_PITCH;         // 34816  [4][2048]
constexpr int P_HS  = P_XS + BBP * T;       // 43008  hs[2][4][128] double buffer
constexpr int P_END = P_HS + 2 * BBP * H1;  // 44032 floats

// consumer layout (R9): Ws2[256][36] | hcat[4][192] | gs2[4][256] | bsm | stage
constexpr int C_PITCH = 36;
constexpr int C_WS   = 0;
constexpr int C_HC   = G2 * C_PITCH;        // 9216
constexpr int C_GS   = C_HC + BBP * 192;    // 9984
constexpr int C_BS   = C_GS + BBP * G2;     // 11008
constexpr int C_ST   = C_BS + G2;           // 11264

constexpr size_t SMEM_MAX = (size_t)P_END * sizeof(float);  // 176128

__device__ float g_h1seq[(size_t)B * T * H1];
__device__ int   g_flag[NP];
__device__ int   g_done[NC];

// ---------------------------------------------------------------------------
__device__ __forceinline__ void fma2(unsigned long long& acc,
                                     unsigned long long a,
                                     unsigned long long b) {
    asm("fma.rn.f32x2 %0, %1, %2, %0;" : "+l"(acc) : "l"(a), "l"(b));
}
__device__ __forceinline__ float f32x2_sum2(unsigned long long u,
                                            unsigned long long v) {
    unsigned long long s;
    asm("add.rn.f32x2 %0, %1, %2;" : "=l"(s) : "l"(u), "l"(v));
    float lo, hi;
    asm("mov.b64 {%0, %1}, %2;" : "=f"(lo), "=f"(hi) : "l"(s));
    return lo + hi;
}
__device__ __forceinline__ float sigmoid_fast(float x) {
    return __fdividef(1.0f, 1.0f + __expf(-x));
}
__device__ __forceinline__ float tanh_acc(float x) {
    return fmaf(2.0f, sigmoid_fast(2.0f * x), -1.0f);
}
__device__ __forceinline__ int ld_acquire(const int* p) {
    int v;
    asm volatile("ld.acquire.gpu.global.b32 %0, [%1];" : "=r"(v) : "l"(p) : "memory");
    return v;
}
__device__ __forceinline__ void st_release(int* p, int v) {
    asm volatile("st.release.gpu.global.b32 [%0], %1;" :: "l"(p), "r"(v) : "memory");
}

// 2 weight rows x 4 batch h streams (16 fma2 / iter); h loaded once
template <int N>
__device__ __forceinline__ void dot4x2(const ulonglong2* __restrict__ wA,
                                       const ulonglong2* __restrict__ wB,
                                       const float* h0, const float* h1,
                                       const float* h2, const float* h3,
                                       unsigned long long* acc /*[16]*/)
{
    const ulonglong2* p0 = reinterpret_cast<const ulonglong2*>(h0);
    const ulonglong2* p1 = reinterpret_cast<const ulonglong2*>(h1);
    const ulonglong2* p2 = reinterpret_cast<const ulonglong2*>(h2);
    const ulonglong2* p3 = reinterpret_cast<const ulonglong2*>(h3);
    #pragma unroll
    for (int i = 0; i < N; i++) {
        ulonglong2 wa = wA[i], wb = wB[i];
        ulonglong2 q0 = p0[i], q1 = p1[i], q2 = p2[i], q3 = p3[i];
        fma2(acc[0],  wa.x, q0.x); fma2(acc[1],  wa.y, q0.y);
        fma2(acc[2],  wa.x, q1.x); fma2(acc[3],  wa.y, q1.y);
        fma2(acc[4],  wa.x, q2.x); fma2(acc[5],  wa.y, q2.y);
        fma2(acc[6],  wa.x, q3.x); fma2(acc[7],  wa.y, q3.y);
        fma2(acc[8],  wb.x, q0.x); fma2(acc[9],  wb.y, q0.y);
        fma2(acc[10], wb.x, q1.x); fma2(acc[11], wb.y, q1.y);
        fma2(acc[12], wb.x, q2.x); fma2(acc[13], wb.y, q2.y);
        fma2(acc[14], wb.x, q3.x); fma2(acc[15], wb.y, q3.y);
    }
}

// 1 weight row x 4 batch h streams (8 fma2 / iter)
template <int N>
__device__ __forceinline__ void dot4(const ulonglong2* __restrict__ w,
                                     const float* h0, const float* h1,
                                     const float* h2, const float* h3,
                                     unsigned long long* acc /*[8]*/)
{
    const ulonglong2* p0 = reinterpret_cast<const ulonglong2*>(h0);
    const ulonglong2* p1 = reinterpret_cast<const ulonglong2*>(h1);
    const ulonglong2* p2 = reinterpret_cast<const ulonglong2*>(h2);
    const ulonglong2* p3 = reinterpret_cast<const ulonglong2*>(h3);
    #pragma unroll
    for (int i = 0; i < N; i++) {
        ulonglong2 wv = w[i];
        ulonglong2 q0 = p0[i], q1 = p1[i], q2 = p2[i], q3 = p3[i];
        fma2(acc[0], wv.x, q0.x); fma2(acc[1], wv.y, q0.y);
        fma2(acc[2], wv.x, q1.x); fma2(acc[3], wv.y, q1.y);
        fma2(acc[4], wv.x, q2.x); fma2(acc[5], wv.y, q2.y);
        fma2(acc[6], wv.x, q3.x); fma2(acc[7], wv.y, q3.y);
    }
}

// ---------------------------------------------------------------------------
__global__ __launch_bounds__(256, 1)
void fused_lstm_kernel(const float* __restrict__ x,
                       const float* __restrict__ W_ih1,
                       const float* __restrict__ W_hh1,
                       const float* __restrict__ b_ih1,
                       const float* __restrict__ b_hh1,
                       const float* __restrict__ W_ih2,
                       const float* __restrict__ W_hh2,
                       const float* __restrict__ b_ih2,
                       const float* __restrict__ b_hh2,
                       const float* __restrict__ W_fc1,
                       const float* __restrict__ b_fc1,
                       const float* __restrict__ W_fc2,
                       const float* __restrict__ b_fc2,
                       float* __restrict__ out)
{
    extern __shared__ float sm[];
    const int tid = threadIdx.x;

    if (blockIdx.x < NP) {
        // ================= PRODUCER: layer 1, 4 batch elems =================
        const int pb = blockIdx.x;
        const int bg = pb * BBP;
        float* Ws = sm + P_WS;
        float* xs = sm + P_XS;
        float* hs = sm + P_HS;          // [2][4][128] double buffer

        // lane-pair mapping: m = tid>>1, rp = tid&1
        const int m  = tid >> 1;
        const int rp = tid & 1;
        const int r0 = m + rp * 128;          // rp0: i-row m   | rp1: f-row m+128
        const int r1 = r0 + 256;              // rp0: g-row m+256 | rp1: o-row m+384

        // smem weights: cols [0,64) of every row
        for (int i = tid; i < G1 * 64; i += 256) {
            int r = i >> 6, c = i & 63;
            Ws[r * P_PITCH + c] = W_hh1[r * H1 + c];
        }
        // reg weights: cols [64,128) of rows r0, r1
        ulonglong2 wrA[16], wrB[16];
        {
            const ulonglong2* sA = reinterpret_cast<const ulonglong2*>(W_hh1 + r0 * H1 + 64);
            const ulonglong2* sB = reinterpret_cast<const ulonglong2*>(W_hh1 + r1 * H1 + 64);
            #pragma unroll
            for (int j = 0; j < 16; j++) { wrA[j] = sA[j]; wrB[j] = sB[j]; }
        }
        const float wx0 = W_ih1[r0], wx1 = W_ih1[r1];
        const float b0  = b_ih1[r0] + b_hh1[r0];
        const float b1  = b_ih1[r1] + b_hh1[r1];

        for (int i = tid; i < BBP * T; i += 256)
            xs[i] = x[(size_t)bg * T + i];
        // zero both h buffers
        for (int i = tid; i < 2 * BBP * H1; i += 256)
            hs[i] = 0.0f;
        __syncthreads();

        float cst[BBP] = {0.0f, 0.0f, 0.0f, 0.0f};   // even lanes only (slot m)

        const ulonglong2* wsA = reinterpret_cast<const ulonglong2*>(Ws + r0 * P_PITCH);
        const ulonglong2* wsB = reinterpret_cast<const ulonglong2*>(Ws + r1 * P_PITCH);

        for (int t = 0; t < T; t++) {
            const float* hb = hs + (t & 1) * 512;        // read buffer
            float*       hn = hs + ((t + 1) & 1) * 512;  // write buffer

            unsigned long long acc[16];
            #pragma unroll
            for (int j = 0; j < 16; j++) acc[j] = 0ull;

            dot4x2<16>(wsA, wsB, hb, hb + 128, hb + 256, hb + 384, acc);           // k [0,64)
            dot4x2<16>(wrA, wrB, hb + 64, hb + 192, hb + 320, hb + 448, acc);      // k [64,128)

            float a0[BBP], a1[BBP];
            #pragma unroll
            for (int bb = 0; bb < BBP; bb++) {
                float xv = xs[bb * T + t];
                float v0 = fmaf(xv, wx0, b0) + f32x2_sum2(acc[2 * bb],     acc[2 * bb + 1]);
                float v1 = fmaf(xv, wx1, b1) + f32x2_sum2(acc[8 + 2 * bb], acc[8 + 2 * bb + 1]);
                a0[bb] = sigmoid_fast(v0);                       // i (rp0) / f (rp1)
                a1[bb] = rp ? sigmoid_fast(v1) : tanh_acc(v1);   // o (rp1) / g (rp0)
            }

            // lane-pair exchange: even lane receives f,o from its odd partner
            #pragma unroll
            for (int bb = 0; bb < BBP; bb++) {
                float fr = __shfl_xor_sync(0xFFFFFFFFu, a0[bb], 1);
                float oc = __shfl_xor_sync(0xFFFFFFFFu, a1[bb], 1);
                if (rp == 0) {
                    float c  = fmaf(fr, cst[bb], a0[bb] * a1[bb]);
                    cst[bb]  = c;
                    float h  = oc * tanh_acc(c);
                    hn[bb * 128 + m] = h;
                    g_h1seq[((size_t)(bg + bb) * T + t) * H1 + m] = h;
                }
            }
            __syncthreads();
            if (tid == 0) st_release(&g_flag[pb], t + 1);
        }

        if (tid == 0) {
            while (ld_acquire(&g_done[pb]) == 0) { __nanosleep(128); }
            g_flag[pb] = 0;
            g_done[pb] = 0;
        }
    } else {
        // ================= CONSUMER: layer 2 + FC, 4 batch elems (R9) =======
        const int cb = blockIdx.x - NP;
        const int bg = cb * BBP;
        float* Ws2   = sm + C_WS;
        float* hcat  = sm + C_HC;     // [4][192] : h1 | h2
        float* gs2   = sm + C_GS;     // [4][256]
        float* bsm   = sm + C_BS;
        float* stage = sm + C_ST;

        const int r = tid;            // gate row 0..255

        // reg weights: concat row [0,160) = W_ih2[r][0:128) + W_hh2[r][0:32)
        ulonglong2 wr[40];
        {
            const ulonglong2* sa = reinterpret_cast<const ulonglong2*>(W_ih2 + r * H1);
            #pragma unroll
            for (int j = 0; j < 32; j++) wr[j] = sa[j];
            const ulonglong2* sb = reinterpret_cast<const ulonglong2*>(W_hh2 + r * H2);
            #pragma unroll
            for (int j = 0; j < 8; j++) wr[32 + j] = sb[j];
        }
        // smem weights: concat [160,192) = W_hh2[r][32:64)
        {
            float* wrow = Ws2 + tid * C_PITCH;
            const float4* src = reinterpret_cast<const float4*>(W_hh2 + r * H2 + 32);
            #pragma unroll
            for (int j = 0; j < 8; j++)
                reinterpret_cast<float4*>(wrow)[j] = src[j];
        }
        bsm[tid] = b_ih2[tid] + b_hh2[tid];
        {
            int bb = tid >> 6, mm = tid & (H2 - 1);
            hcat[bb * 192 + H1 + mm] = 0.0f;
        }
        __syncthreads();

        float cst = 0.0f;                 // update state for (tid>>6, tid&63)
        const int ub = tid >> 6;
        const int um = tid & (H2 - 1);
        const bool is_g = (r >= 2 * H2) && (r < 3 * H2);
        const ulonglong2* ws = reinterpret_cast<const ulonglong2*>(Ws2 + tid * C_PITCH);

        for (int t = 0; t < T; t++) {
            if (tid == 0) {
                while (ld_acquire(&g_flag[cb]) < t + 1) { __nanosleep(32); }
            }
            __syncthreads();

            // stage h1(t): 2 slots per thread
            {
                int s0 = tid, s1 = tid + 256;
                int b0 = s0 >> 7, m0 = s0 & (H1 - 1);
                int b1 = s1 >> 7, m1 = s1 & (H1 - 1);
                hcat[b0 * 192 + m0] = __ldcg(&g_h1seq[((size_t)(bg + b0) * T + t) * H1 + m0]);
                hcat[b1 * 192 + m1] = __ldcg(&g_h1seq[((size_t)(bg + b1) * T + t) * H1 + m1]);
            }
            __syncthreads();

            unsigned long long acc[8];
            #pragma unroll
            for (int j = 0; j < 8; j++) acc[j] = 0ull;
            dot4<40>(wr, hcat, hcat + 192, hcat + 384, hcat + 576, acc);           // k [0,160)
            dot4<8>(ws, hcat + 160, hcat + 352, hcat + 544, hcat + 736, acc);      // k [160,192)

            #pragma unroll
            for (int bb = 0; bb < BBP; bb++) {
                float v = bsm[r] + f32x2_sum2(acc[2 * bb], acc[2 * bb + 1]);
                gs2[bb * G2 + r] = is_g ? tanh_acc(v) : sigmoid_fast(v);
            }
            __syncthreads();

            {
                const float* gb = gs2 + ub * G2;
                float i_ = gb[um], f_ = gb[H2 + um], gg = gb[2 * H2 + um], o_ = gb[3 * H2 + um];
                cst = fmaf(f_, cst, i_ * gg);
                hcat[ub * 192 + H1 + um] = o_ * tanh_acc(cst);
            }
            __syncthreads();
        }

        // ---- FC head on final h2 ----
        if (tid < BBP * 25) {
            int bb = tid / 25;
            int i  = tid - bb * 25;
            float a = b_fc1[i];
            #pragma unroll 4
            for (int k = 0; k < H2; k++)
                a = fmaf(W_fc1[i * H2 + k], hcat[bb * 192 + H1 + k], a);
            stage[bb * 32 + i] = a;
        }
        __syncthreads();
        if (tid < BBP) {
            float a = b_fc2[0];
            #pragma unroll 5
            for (int i = 0; i < 25; i++)
                a = fmaf(W_fc2[i], stage[tid * 32 + i], a);
            out[bg + tid] = a;
        }
        if (tid == 0) st_release(&g_done[cb], 1);
    }
}

// ---------------------------------------------------------------------------
extern "C" void kernel_launch(void* const* d_in, const int* in_sizes, int n_in,
                              void* d_out, int out_size)
{
    const float* x     = (const float*)d_in[0];
    const float* W_ih1 = (const float*)d_in[1];
    const float* W_hh1 = (const float*)d_in[2];
    const float* b_ih1 = (const float*)d_in[3];
    const float* b_hh1 = (const float*)d_in[4];
    const float* W_ih2 = (const float*)d_in[5];
    const float* W_hh2 = (const float*)d_in[6];
    const float* b_ih2 = (const float*)d_in[7];
    const float* b_hh2 = (const float*)d_in[8];
    const float* W_fc1 = (const float*)d_in[9];
    const float* b_fc1 = (const float*)d_in[10];
    const float* W_fc2 = (const float*)d_in[11];
    const float* b_fc2 = (const float*)d_in[12];
    float* out = (float*)d_out;

    static bool attr_done = false;
    if (!attr_done) {
        cudaFuncSetAttribute(fused_lstm_kernel,
                             cudaFuncAttributeMaxDynamicSharedMemorySize, (int)SMEM_MAX);
        attr_done = true;
    }

    fused_lstm_kernel<<<NP + NC, 256, SMEM_MAX>>>(
        x, W_ih1, W_hh1, b_ih1, b_hh1,
        W_ih2, W_hh2, b_ih2, b_hh2,
        W_fc1, b_fc1, W_fc2, b_fc2, out);
}

// round 16
// speedup vs baseline: 1.5106x; 1.1645x over previous
#include <cuda_runtime.h>
#include <cstddef>

// ---------------------------------------------------------------------------
// StockPredictor: 2-layer LSTM (B=256, T=2048, D=1, H1=128, H2=64) + FC head.
// R16 = R9 exactly (best measured: 64 producers / 64 consumers x 4 batches,
// 256 thr, producer 2 rows/thr 64smem/64reg, consumer 160reg/32smem) with:
//   - consumer end-of-loop barrier removed (redundant; ordering provided by
//     the two barriers at the top of the next iteration) => 3 barriers/step
//   - polite __nanosleep polling on all spin loops
//   - FC head unroll-limited (cold code must not inflate regs)
// ---------------------------------------------------------------------------

constexpr int T  = 2048;
constexpr int B  = 256;
constexpr int H1 = 128;
constexpr int G1 = 4 * H1;   // 512
constexpr int H2 = 64;
constexpr int G2 = 4 * H2;   // 256
constexpr int NP = 64;       // producer blocks
constexpr int NC = 64;       // consumer blocks
constexpr int BBP = 4;       // batch elems per block

// Producer smem layout (float offsets)
constexpr int P_PITCH = 68;                 // 17*16B odd -> conflict-free LDS.128
constexpr int P_WS  = 0;                    // [512][68]
constexpr int P_XS  = G1 * P_PITCH;         // 34816  [4][2048]
constexpr int P_HS  = P_XS + BBP * T;       // 43008  [4][128]
constexpr int P_GS  = P_HS + BBP * H1;      // 43520  [4][512]
constexpr int P_END = P_GS + BBP * G1;      // 45568 floats = 182272 B

// Consumer smem layout (float offsets)
constexpr int C_PITCH = 36;                 // 9*16B odd
constexpr int C_WS   = 0;                   // [256][36]
constexpr int C_HC   = G2 * C_PITCH;        // 9216   hcat[4][192]
constexpr int C_GS   = C_HC + BBP * 192;    // 9984   [4][256]
constexpr int C_BS   = C_GS + BBP * G2;     // 11008  [256]
constexpr int C_ST   = C_BS + G2;           // 11264  [4][32] FC staging

constexpr size_t SMEM_MAX = (size_t)P_END * sizeof(float);  // 182272

// scratch + sync (zero-initialized at module load; reset by end handshake)
__device__ float g_h1seq[(size_t)B * T * H1];
__device__ int   g_flag[NP];
__device__ int   g_done[NC];

// ---------------------------------------------------------------------------
__device__ __forceinline__ void fma2(unsigned long long& acc,
                                     unsigned long long a,
                                     unsigned long long b) {
    asm("fma.rn.f32x2 %0, %1, %2, %0;" : "+l"(acc) : "l"(a), "l"(b));
}
__device__ __forceinline__ float f32x2_sum2(unsigned long long u,
                                            unsigned long long v) {
    unsigned long long s;
    asm("add.rn.f32x2 %0, %1, %2;" : "=l"(s) : "l"(u), "l"(v));
    float lo, hi;
    asm("mov.b64 {%0, %1}, %2;" : "=f"(lo), "=f"(hi) : "l"(s));
    return lo + hi;
}
__device__ __forceinline__ float sigmoid_fast(float x) {
    return __fdividef(1.0f, 1.0f + __expf(-x));
}
__device__ __forceinline__ float tanh_acc(float x) {
    return fmaf(2.0f, sigmoid_fast(2.0f * x), -1.0f);
}
__device__ __forceinline__ int ld_acquire(const int* p) {
    int v;
    asm volatile("ld.acquire.gpu.global.b32 %0, [%1];" : "=r"(v) : "l"(p) : "memory");
    return v;
}
__device__ __forceinline__ void st_release(int* p, int v) {
    asm volatile("st.release.gpu.global.b32 [%0], %1;" :: "l"(p), "r"(v) : "memory");
}

// 1 weight row x 4 batch h streams (8 fma2 / iter)
template <int N>
__device__ __forceinline__ void dot4(const ulonglong2* __restrict__ w,
                                     const float* h0, const float* h1,
                                     const float* h2, const float* h3,
                                     unsigned long long* acc /*[8]*/)
{
    const ulonglong2* p0 = reinterpret_cast<const ulonglong2*>(h0);
    const ulonglong2* p1 = reinterpret_cast<const ulonglong2*>(h1);
    const ulonglong2* p2 = reinterpret_cast<const ulonglong2*>(h2);
    const ulonglong2* p3 = reinterpret_cast<const ulonglong2*>(h3);
    #pragma unroll
    for (int i = 0; i < N; i++) {
        ulonglong2 wv = w[i];
        ulonglong2 q0 = p0[i], q1 = p1[i], q2 = p2[i], q3 = p3[i];
        fma2(acc[0], wv.x, q0.x); fma2(acc[1], wv.y, q0.y);
        fma2(acc[2], wv.x, q1.x); fma2(acc[3], wv.y, q1.y);
        fma2(acc[4], wv.x, q2.x); fma2(acc[5], wv.y, q2.y);
        fma2(acc[6], wv.x, q3.x); fma2(acc[7], wv.y, q3.y);
    }
}

// 2 weight rows x 4 batch h streams (16 fma2 / iter); h loaded once
template <int N>
__device__ __forceinline__ void dot4x2(const ulonglong2* __restrict__ wA,
                                       const ulonglong2* __restrict__ wB,
                                       const float* h0, const float* h1,
                                       const float* h2, const float* h3,
                                       unsigned long long* acc /*[16]*/)
{
    const ulonglong2* p0 = reinterpret_cast<const ulonglong2*>(h0);
    const ulonglong2* p1 = reinterpret_cast<const ulonglong2*>(h1);
    const ulonglong2* p2 = reinterpret_cast<const ulonglong2*>(h2);
    const ulonglong2* p3 = reinterpret_cast<const ulonglong2*>(h3);
    #pragma unroll
    for (int i = 0; i < N; i++) {
        ulonglong2 wa = wA[i], wb = wB[i];
        ulonglong2 q0 = p0[i], q1 = p1[i], q2 = p2[i], q3 = p3[i];
        fma2(acc[0],  wa.x, q0.x); fma2(acc[1],  wa.y, q0.y);
        fma2(acc[2],  wa.x, q1.x); fma2(acc[3],  wa.y, q1.y);
        fma2(acc[4],  wa.x, q2.x); fma2(acc[5],  wa.y, q2.y);
        fma2(acc[6],  wa.x, q3.x); fma2(acc[7],  wa.y, q3.y);
        fma2(acc[8],  wb.x, q0.x); fma2(acc[9],  wb.y, q0.y);
        fma2(acc[10], wb.x, q1.x); fma2(acc[11], wb.y, q1.y);
        fma2(acc[12], wb.x, q2.x); fma2(acc[13], wb.y, q2.y);
        fma2(acc[14], wb.x, q3.x); fma2(acc[15], wb.y, q3.y);
    }
}

// ---------------------------------------------------------------------------
__global__ __launch_bounds__(256, 1)
void fused_lstm_kernel(const float* __restrict__ x,
                       const float* __restrict__ W_ih1,
                       const float* __restrict__ W_hh1,
                       const float* __restrict__ b_ih1,
                       const float* __restrict__ b_hh1,
                       const float* __restrict__ W_ih2,
                       const float* __restrict__ W_hh2,
                       const float* __restrict__ b_ih2,
                       const float* __restrict__ b_hh2,
                       const float* __restrict__ W_fc1,
                       const float* __restrict__ b_fc1,
                       const float* __restrict__ W_fc2,
                       const float* __restrict__ b_fc2,
                       float* __restrict__ out)
{
    extern __shared__ float sm[];
    const int tid = threadIdx.x;

    if (blockIdx.x < NP) {
        // ================= PRODUCER: layer 1, 4 batch elems (R9) ============
        const int pb = blockIdx.x;
        const int bg = pb * BBP;
        float* Ws = sm + P_WS;
        float* xs = sm + P_XS;
        float* hs = sm + P_HS;
        float* gs = sm + P_GS;

        // rows owned: rA = tid, rB = tid + 256
        const int rA = tid, rB = tid + 256;

        // smem weights: cols [0,64) of every row
        for (int i = tid; i < G1 * 64; i += 256) {
            int r = i >> 6, c = i & 63;
            Ws[r * P_PITCH + c] = W_hh1[r * H1 + c];
        }
        // reg weights: cols [64,128) of rows rA, rB
        ulonglong2 wrA[16], wrB[16];
        {
            const ulonglong2* sA = reinterpret_cast<const ulonglong2*>(W_hh1 + rA * H1 + 64);
            const ulonglong2* sB = reinterpret_cast<const ulonglong2*>(W_hh1 + rB * H1 + 64);
            #pragma unroll
            for (int j = 0; j < 16; j++) { wrA[j] = sA[j]; wrB[j] = sB[j]; }
        }
        const float wxA = W_ih1[rA], wxB = W_ih1[rB];
        const float bA  = b_ih1[rA] + b_hh1[rA];
        const float bB  = b_ih1[rB] + b_hh1[rB];

        for (int i = tid; i < BBP * T; i += 256)
            xs[i] = x[(size_t)bg * T + i];
        hs[tid] = 0.0f; hs[tid + 256] = 0.0f;
        __syncthreads();

        // update-state: slots s0=tid (bb=tid>>7), s1=tid+256 (bb+2)
        float cst0 = 0.0f, cst1 = 0.0f;
        const int ub = tid >> 7;         // 0..1
        const int um = tid & (H1 - 1);
        const bool isgB = (tid < 128);   // rB in [256,384) -> g gate

        const ulonglong2* wsA = reinterpret_cast<const ulonglong2*>(Ws + rA * P_PITCH);
        const ulonglong2* wsB = reinterpret_cast<const ulonglong2*>(Ws + rB * P_PITCH);

        for (int t = 0; t < T; t++) {
            unsigned long long acc[16];
            #pragma unroll
            for (int j = 0; j < 16; j++) acc[j] = 0ull;

            dot4x2<16>(wsA, wsB, hs, hs + 128, hs + 256, hs + 384, acc);      // k [0,64)
            dot4x2<16>(wrA, wrB, hs + 64, hs + 192, hs + 320, hs + 448, acc); // k [64,128)

            #pragma unroll
            for (int bb = 0; bb < BBP; bb++) {
                float xv = xs[bb * T + t];
                float fA = fmaf(xv, wxA, bA) + f32x2_sum2(acc[2 * bb],     acc[2 * bb + 1]);
                float fB = fmaf(xv, wxB, bB) + f32x2_sum2(acc[8 + 2 * bb], acc[8 + 2 * bb + 1]);
                // rA in [0,256): i/f gates -> sigmoid always
                gs[bb * G1 + rA] = sigmoid_fast(fA);
                gs[bb * G1 + rB] = isgB ? tanh_acc(fB) : sigmoid_fast(fB);
            }
            __syncthreads();

            // update: 2 slots per thread: (ub, um) and (ub+2, um)
            {
                const float* g0 = gs + ub * G1;
                float i0 = g0[um], f0 = g0[H1 + um], gg0 = g0[2 * H1 + um], o0 = g0[3 * H1 + um];
                cst0 = fmaf(f0, cst0, i0 * gg0);
                float h0v = o0 * tanh_acc(cst0);
                hs[tid] = h0v;
                g_h1seq[((size_t)(bg + ub) * T + t) * H1 + um] = h0v;

                const float* g1 = gs + (ub + 2) * G1;
                float i1 = g1[um], f1 = g1[H1 + um], gg1 = g1[2 * H1 + um], o1 = g1[3 * H1 + um];
                cst1 = fmaf(f1, cst1, i1 * gg1);
                float h1v = o1 * tanh_acc(cst1);
                hs[tid + 256] = h1v;
                g_h1seq[((size_t)(bg + ub + 2) * T + t) * H1 + um] = h1v;
            }
            __syncthreads();
            if (tid == 0) st_release(&g_flag[pb], t + 1);
        }

        // end handshake: wait for consumer, then reset flags for next replay
        if (tid == 0) {
            while (ld_acquire(&g_done[pb]) == 0) { __nanosleep(128); }
            g_flag[pb] = 0;
            g_done[pb] = 0;
        }
    } else {
        // ================= CONSUMER: layer 2 + FC, 4 batch elems ============
        const int cb = blockIdx.x - NP;
        const int bg = cb * BBP;
        float* Ws2   = sm + C_WS;
        float* hcat  = sm + C_HC;     // [4][192] : h1 | h2
        float* gs2   = sm + C_GS;     // [4][256]
        float* bsm   = sm + C_BS;
        float* stage = sm + C_ST;

        const int r = tid;            // gate row 0..255

        // reg weights: concat row [0,160) = W_ih2[r][0:128) + W_hh2[r][0:32)
        ulonglong2 wr[40];
        {
            const ulonglong2* sa = reinterpret_cast<const ulonglong2*>(W_ih2 + r * H1);
            #pragma unroll
            for (int j = 0; j < 32; j++) wr[j] = sa[j];
            const ulonglong2* sb = reinterpret_cast<const ulonglong2*>(W_hh2 + r * H2);
            #pragma unroll
            for (int j = 0; j < 8; j++) wr[32 + j] = sb[j];
        }
        // smem weights: concat [160,192) = W_hh2[r][32:64)
        {
            float* wrow = Ws2 + tid * C_PITCH;
            const float4* src = reinterpret_cast<const float4*>(W_hh2 + r * H2 + 32);
            #pragma unroll
            for (int j = 0; j < 8; j++)
                reinterpret_cast<float4*>(wrow)[j] = src[j];
        }
        bsm[tid] = b_ih2[tid] + b_hh2[tid];
        // zero h2 region
        {
            int bb = tid >> 6, m = tid & (H2 - 1);
            hcat[bb * 192 + H1 + m] = 0.0f;
        }
        __syncthreads();

        float cst = 0.0f;                 // update state for (tid>>6, tid&63)
        const int ub = tid >> 6;
        const int um = tid & (H2 - 1);
        const bool is_g = (r >= 2 * H2) && (r < 3 * H2);
        const ulonglong2* ws = reinterpret_cast<const ulonglong2*>(Ws2 + tid * C_PITCH);

        for (int t = 0; t < T; t++) {
            if (tid == 0) {
                while (ld_acquire(&g_flag[cb]) < t + 1) { __nanosleep(32); }
            }
            __syncthreads();   // barrier 1: flag verified for all

            // stage h1(t): 2 slots per thread
            {
                int s0 = tid, s1 = tid + 256;
                int b0 = s0 >> 7, m0 = s0 & (H1 - 1);
                int b1 = s1 >> 7, m1 = s1 & (H1 - 1);
                hcat[b0 * 192 + m0] = __ldcg(&g_h1seq[((size_t)(bg + b0) * T + t) * H1 + m0]);
                hcat[b1 * 192 + m1] = __ldcg(&g_h1seq[((size_t)(bg + b1) * T + t) * H1 + m1]);
            }
            __syncthreads();   // barrier 2: hcat h1 ready

            unsigned long long acc[8];
            #pragma unroll
            for (int j = 0; j < 8; j++) acc[j] = 0ull;
            dot4<40>(wr, hcat, hcat + 192, hcat + 384, hcat + 576, acc);            // k [0,160)
            dot4<8>(ws, hcat + 160, hcat + 352, hcat + 544, hcat + 736, acc);       // k [160,192)

            #pragma unroll
            for (int bb = 0; bb < BBP; bb++) {
                float v = bsm[r] + f32x2_sum2(acc[2 * bb], acc[2 * bb + 1]);
                gs2[bb * G2 + r] = is_g ? tanh_acc(v) : sigmoid_fast(v);
            }
            __syncthreads();   // barrier 3: gates ready

            // update: one (bb,m) slot per thread.
            // NOTE: no end-of-loop barrier. update(t) writes hcat[h2]/reads gs2;
            // the next iteration's barriers 1+2 (block-wide) order these against
            // fma(t+1) reads and gates(t+1) writes. Safe by construction.
            {
                const float* gb = gs2 + ub * G2;
                float i_ = gb[um], f_ = gb[H2 + um], gg = gb[2 * H2 + um], o_ = gb[3 * H2 + um];
                cst = fmaf(f_, cst, i_ * gg);
                hcat[ub * 192 + H1 + um] = o_ * tanh_acc(cst);
            }
        }
        __syncthreads();       // final: h2 complete before FC head

        // ---- FC head on final h2 (unroll-limited; cold code) ----
        if (tid < BBP * 25) {
            int bb = tid / 25;
            int i  = tid - bb * 25;
            float a = b_fc1[i];
            #pragma unroll 4
            for (int k = 0; k < H2; k++)
                a = fmaf(W_fc1[i * H2 + k], hcat[bb * 192 + H1 + k], a);
            stage[bb * 32 + i] = a;
        }
        __syncthreads();
        if (tid < BBP) {
            float a = b_fc2[0];
            #pragma unroll 5
            for (int i = 0; i < 25; i++)
                a = fmaf(W_fc2[i], stage[tid * 32 + i], a);
            out[bg + tid] = a;
        }
        if (tid == 0) st_release(&g_done[cb], 1);
    }
}

// ---------------------------------------------------------------------------
extern "C" void kernel_launch(void* const* d_in, const int* in_sizes, int n_in,
                              void* d_out, int out_size)
{
    const float* x     = (const float*)d_in[0];
    const float* W_ih1 = (const float*)d_in[1];
    const float* W_hh1 = (const float*)d_in[2];
    const float* b_ih1 = (const float*)d_in[3];
    const float* b_hh1 = (const float*)d_in[4];
    const float* W_ih2 = (const float*)d_in[5];
    const float* W_hh2 = (const float*)d_in[6];
    const float* b_ih2 = (const float*)d_in[7];
    const float* b_hh2 = (const float*)d_in[8];
    const float* W_fc1 = (const float*)d_in[9];
    const float* b_fc1 = (const float*)d_in[10];
    const float* W_fc2 = (const float*)d_in[11];
    const float* b_fc2 = (const float*)d_in[12];
    float* out = (float*)d_out;

    static bool attr_done = false;
    if (!attr_done) {
        cudaFuncSetAttribute(fused_lstm_kernel,
                             cudaFuncAttributeMaxDynamicSharedMemorySize, (int)SMEM_MAX);
        attr_done = true;
    }

    fused_lstm_kernel<<<NP + NC, 256, SMEM_MAX>>>(
        x, W_ih1, W_hh1, b_ih1, b_hh1,
        W_ih2, W_hh2, b_ih2, b_hh2,
        W_fc1, b_fc1, W_fc2, b_fc2, out);
}